// round 1
// baseline (speedup 1.0000x reference)
#include <cuda_runtime.h>
#include <cstdint>

// Problem shape (fixed): T=1024, B=128, F=512
//   xs[t,b,g] = sum_f spikes[t,b,f] * W[g,f]   -> GEMM  M=131072, N=512, K=512
//   then sequential LIF scan over t, output final (z, z, v, i), each [128,512].

#define Tn 1024
#define Bn 128
#define Fn 512
#define Mrows (Tn * Bn)          // 131072
#define NEURONS (Bn * Fn)        // 65536

// 268 MB scratch for xs (module-scope device array: allowed, not a runtime alloc)
__device__ float g_xs[(size_t)Tn * Bn * Fn];

// ---------------------------------------------------------------------------
// SGEMM:  C[M,512] = A[M,512] * W[512,512]^T   (both K-major, K=512)
// CTA tile 128x128, BK=16, 256 threads, 8x8 per-thread microtile.
// ---------------------------------------------------------------------------
__global__ __launch_bounds__(256, 2)
void sgemm_nt_kernel(const float* __restrict__ A,
                     const float* __restrict__ W)
{
    __shared__ float As[16][128];
    __shared__ float Bs[16][128];

    const int tid  = threadIdx.x;
    const int tx   = tid & 15;          // 0..15 -> output cols tx*8..tx*8+7
    const int ty   = tid >> 4;          // 0..15 -> output rows ty*8..ty*8+7
    const int row0 = blockIdx.y * 128;
    const int col0 = blockIdx.x * 128;

    // loading layout: 512 float4 per 128x16 tile, 2 per thread
    const int lrow = tid >> 2;          // 0..63
    const int lk4  = (tid & 3) * 4;     // k offset 0,4,8,12

    const float* Ap = A + (size_t)(row0 + lrow) * Fn + lk4;
    const float* Wp = W + (size_t)(col0 + lrow) * Fn + lk4;

    float4 ra0 = *(const float4*)(Ap);
    float4 ra1 = *(const float4*)(Ap + 64 * Fn);
    float4 rw0 = *(const float4*)(Wp);
    float4 rw1 = *(const float4*)(Wp + 64 * Fn);

    float acc[8][8];
#pragma unroll
    for (int i = 0; i < 8; i++)
#pragma unroll
        for (int j = 0; j < 8; j++) acc[i][j] = 0.0f;

    for (int kt = 0; kt < Fn; kt += 16) {
        // stage registers -> smem (transposed to [k][row])
        As[lk4 + 0][lrow]      = ra0.x;
        As[lk4 + 1][lrow]      = ra0.y;
        As[lk4 + 2][lrow]      = ra0.z;
        As[lk4 + 3][lrow]      = ra0.w;
        As[lk4 + 0][lrow + 64] = ra1.x;
        As[lk4 + 1][lrow + 64] = ra1.y;
        As[lk4 + 2][lrow + 64] = ra1.z;
        As[lk4 + 3][lrow + 64] = ra1.w;

        Bs[lk4 + 0][lrow]      = rw0.x;
        Bs[lk4 + 1][lrow]      = rw0.y;
        Bs[lk4 + 2][lrow]      = rw0.z;
        Bs[lk4 + 3][lrow]      = rw0.w;
        Bs[lk4 + 0][lrow + 64] = rw1.x;
        Bs[lk4 + 1][lrow + 64] = rw1.y;
        Bs[lk4 + 2][lrow + 64] = rw1.z;
        Bs[lk4 + 3][lrow + 64] = rw1.w;
        __syncthreads();

        // prefetch next k-tile while computing this one
        if (kt + 16 < Fn) {
            ra0 = *(const float4*)(Ap + kt + 16);
            ra1 = *(const float4*)(Ap + kt + 16 + 64 * Fn);
            rw0 = *(const float4*)(Wp + kt + 16);
            rw1 = *(const float4*)(Wp + kt + 16 + 64 * Fn);
        }

#pragma unroll
        for (int k = 0; k < 16; k++) {
            float4 a0 = *(const float4*)(&As[k][ty * 8]);
            float4 a1 = *(const float4*)(&As[k][ty * 8 + 4]);
            float4 b0 = *(const float4*)(&Bs[k][tx * 8]);
            float4 b1 = *(const float4*)(&Bs[k][tx * 8 + 4]);
            float av[8] = {a0.x, a0.y, a0.z, a0.w, a1.x, a1.y, a1.z, a1.w};
            float bv[8] = {b0.x, b0.y, b0.z, b0.w, b1.x, b1.y, b1.z, b1.w};
#pragma unroll
            for (int i = 0; i < 8; i++)
#pragma unroll
                for (int j = 0; j < 8; j++)
                    acc[i][j] = fmaf(av[i], bv[j], acc[i][j]);
        }
        __syncthreads();
    }

    // write C (g_xs)
#pragma unroll
    for (int i = 0; i < 8; i++) {
        float* cp = g_xs + (size_t)(row0 + ty * 8 + i) * Fn + col0 + tx * 8;
        float4 c0 = {acc[i][0], acc[i][1], acc[i][2], acc[i][3]};
        float4 c1 = {acc[i][4], acc[i][5], acc[i][6], acc[i][7]};
        *(float4*)(cp)     = c0;
        *(float4*)(cp + 4) = c1;
    }
}

// ---------------------------------------------------------------------------
// LIF scan: one thread per neuron, sequential over T with 8-deep x prefetch.
// Matches reference arithmetic:
//   v_dec = v + 0.1*((0 - v) + i); i_dec = i + (-0.2)*i
//   z = (v_dec - 1) > 0 ; v = z ? 0 : v_dec ; i = i_dec + x_t
// ---------------------------------------------------------------------------
__global__ __launch_bounds__(256)
void lif_scan_kernel(float* __restrict__ out)
{
    const int n = blockIdx.x * blockDim.x + threadIdx.x;   // 0..65535
    const float* xp = g_xs + n;

    float v = 0.0f, cur = 0.0f, z = 0.0f;

    float xb[8];
#pragma unroll
    for (int j = 0; j < 8; j++) xb[j] = __ldg(xp + (size_t)j * NEURONS);

    for (int t0 = 0; t0 < Tn; t0 += 8) {
        float xn[8] = {0.f, 0.f, 0.f, 0.f, 0.f, 0.f, 0.f, 0.f};
        if (t0 + 8 < Tn) {
#pragma unroll
            for (int j = 0; j < 8; j++)
                xn[j] = __ldg(xp + (size_t)(t0 + 8 + j) * NEURONS);
        }
#pragma unroll
        for (int j = 0; j < 8; j++) {
            float vd = fmaf(0.1f, cur - v, v);       // v + 0.1*((0-v)+i)
            float id = fmaf(-0.2f, cur, cur);        // i + (-0.2)*i
            bool  sp = (vd - 1.0f) > 0.0f;
            z   = sp ? 1.0f : 0.0f;
            v   = sp ? 0.0f : vd;
            cur = id + xb[j];
        }
#pragma unroll
        for (int j = 0; j < 8; j++) xb[j] = xn[j];
    }

    out[n]               = z;   // z_final
    out[NEURONS + n]     = z;   // z_final (returned twice)
    out[2 * NEURONS + n] = v;   // v_final
    out[3 * NEURONS + n] = cur; // i_final
}

// ---------------------------------------------------------------------------
extern "C" void kernel_launch(void* const* d_in, const int* in_sizes, int n_in,
                              void* d_out, int out_size)
{
    const float* spikes = (const float*)d_in[0];   // [1024,128,512]
    const float* W      = (const float*)d_in[1];   // [512,512]
    float* out          = (float*)d_out;           // 4 * 65536 floats

    dim3 grid(Fn / 128, Mrows / 128);              // (4, 1024)
    sgemm_nt_kernel<<<grid, 256>>>(spikes, W);
    lif_scan_kernel<<<NEURONS / 256, 256>>>(out);
}